// round 12
// baseline (speedup 1.0000x reference)
#include <cuda_runtime.h>
#include <cstdint>

// Problem constants
#define Bq   128        // batch
#define Nn   100000     // bank size
#define Dd   128        // feature dim
#define ROWS 129        // memory_da row stride (label + 128 feats)
#define TILE_N 64
#define NTILES 1563     // ceil(100000/64)

// exp(dot/T) = 2^(dot * log2(e)/T)
#define KLOG2 20.609929155556620f

// smem layout (floats)
#define XS_OFF   0            // xs: [128 d][132] transposed x  (pad 132)
#define FS_OFF   16896        // fs: [128 d][68]  transposed feats tile (pad 68)
#define LAB_OFF  25600        // [64] tile row labels
#define BLAB_OFF 25664        // [128] batch labels as float
#define SMEM_FLOATS 25792
#define SMEM_BYTES  (SMEM_FLOATS * 4)

// scratch (no allocation allowed -> device globals)
__device__ float g_Zpart[NTILES * Bq];
__device__ float g_invZ[Bq];

// ---------------------------------------------------------------------------
// FFMA-only exp2: 2^t for |t| <= ~40, rel err ~2e-6
// ---------------------------------------------------------------------------
__device__ __forceinline__ float exp2_fast(float t) {
    float r = __fadd_rn(t, 12582912.0f);               // round to int (1.5*2^23)
    float f = __fsub_rn(t, __fsub_rn(r, 12582912.0f)); // f in [-0.5, 0.5]
    int   n = __float_as_int(r) - 0x4B400000;
    float p = 0.00133335581f;
    p = fmaf(p, f, 0.00961812910f);
    p = fmaf(p, f, 0.05550410866f);
    p = fmaf(p, f, 0.24022650696f);
    p = fmaf(p, f, 0.69314718056f);
    p = fmaf(p, f, 1.0f);
    return __int_as_float(__float_as_int(p) + (n << 23));
}

// ---------------------------------------------------------------------------
// Main kernel: 128(b) x 64(n) tile per CTA. 128 threads, thread tile 16b x 4n.
// FFMA2 (fma.rn.f32x2) microkernel, accumulator pairs along b.
//   A loads: 8x ld.shared.b64, only 2 distinct addrs per warp (broadcast).
//   B loads: 1x ld.shared.v4, 16 lanes x 16B contiguous (conflict-free).
// ---------------------------------------------------------------------------
__global__ void __launch_bounds__(128, 2)
nce_main(const float* __restrict__ x,
         const int*   __restrict__ labels,
         const float* __restrict__ mda,
         float* __restrict__ outE,
         float* __restrict__ outM)
{
    extern __shared__ float sm[];
    float* xs   = sm + XS_OFF;    // xs[d*132 + b]
    float* fs   = sm + FS_OFF;    // fs[d*68 + n]
    float* labf = sm + LAB_OFF;
    float* blab = sm + BLAB_OFF;

    const int t  = threadIdx.x;   // 0..127
    const int nb = blockIdx.x * TILE_N;

    // ---- stage x (coalesced LDG across t, d = t) ----
    #pragma unroll 4
    for (int b = 0; b < Bq; b++) {
        xs[t * 132 + b] = x[b * Dd + t];
    }
    // ---- stage feats tile (d = t, one bank row per n) ----
    #pragma unroll 4
    for (int n = 0; n < TILE_N; n++) {
        int gn = nb + n;
        fs[t * 68 + n] = (gn < Nn) ? mda[(size_t)gn * ROWS + 1 + t] : 0.0f;
    }
    if (t < TILE_N) {
        int gn = nb + t;
        labf[t] = (gn < Nn) ? mda[(size_t)gn * ROWS] : -1.0f;
    }
    blab[t] = (float)labels[t];
    __syncthreads();

    const int tx = t & 15, ty = t >> 4;  // tx: n-col group, ty: b-row group
    const int b0 = ty * 16, n0 = tx * 4;

    uint32_t xs_sa = (uint32_t)__cvta_generic_to_shared(xs) + (uint32_t)b0 * 4u;
    uint32_t fs_sa = (uint32_t)__cvta_generic_to_shared(fs) + (uint32_t)n0 * 4u;

    unsigned long long acc[8][4];   // [b-pair 0..7][n 0..3]
    #pragma unroll
    for (int i = 0; i < 8; i++)
        #pragma unroll
        for (int j = 0; j < 4; j++) acc[i][j] = 0ULL;

    #pragma unroll 4
    for (int k = 0; k < 128; k++) {
        unsigned long long a2[8];
        uint32_t aa = xs_sa + (uint32_t)k * 528u;      // 132 floats * 4B
        asm("ld.shared.b64 %0, [%1];"     : "=l"(a2[0]) : "r"(aa));
        asm("ld.shared.b64 %0, [%1+8];"   : "=l"(a2[1]) : "r"(aa));
        asm("ld.shared.b64 %0, [%1+16];"  : "=l"(a2[2]) : "r"(aa));
        asm("ld.shared.b64 %0, [%1+24];"  : "=l"(a2[3]) : "r"(aa));
        asm("ld.shared.b64 %0, [%1+32];"  : "=l"(a2[4]) : "r"(aa));
        asm("ld.shared.b64 %0, [%1+40];"  : "=l"(a2[5]) : "r"(aa));
        asm("ld.shared.b64 %0, [%1+48];"  : "=l"(a2[6]) : "r"(aa));
        asm("ld.shared.b64 %0, [%1+56];"  : "=l"(a2[7]) : "r"(aa));

        float bx, by, bz, bw;
        uint32_t fa = fs_sa + (uint32_t)k * 272u;      // 68 floats * 4B
        asm("ld.shared.v4.f32 {%0,%1,%2,%3}, [%4];"
            : "=f"(bx), "=f"(by), "=f"(bz), "=f"(bw) : "r"(fa));

        unsigned long long b2[4];
        asm("mov.b64 %0, {%1,%2};" : "=l"(b2[0]) : "f"(bx), "f"(bx));
        asm("mov.b64 %0, {%1,%2};" : "=l"(b2[1]) : "f"(by), "f"(by));
        asm("mov.b64 %0, {%1,%2};" : "=l"(b2[2]) : "f"(bz), "f"(bz));
        asm("mov.b64 %0, {%1,%2};" : "=l"(b2[3]) : "f"(bw), "f"(bw));

        #pragma unroll
        for (int bp = 0; bp < 8; bp++)
            #pragma unroll
            for (int n = 0; n < 4; n++)
                asm("fma.rn.f32x2 %0, %1, %2, %0;"
                    : "+l"(acc[bp][n]) : "l"(a2[bp]), "l"(b2[n]));
    }

    // ---- epilogue: exp, partial sums, stores ----
    float ev[16][4];
    #pragma unroll
    for (int bp = 0; bp < 8; bp++) {
        #pragma unroll
        for (int n = 0; n < 4; n++) {
            float lo, hi;
            asm("mov.b64 {%0,%1}, %2;" : "=f"(lo), "=f"(hi) : "l"(acc[bp][n]));
            ev[2 * bp + 0][n] = exp2_fast(lo * KLOG2);
            ev[2 * bp + 1][n] = exp2_fast(hi * KLOG2);
        }
    }

    float vmask[4];
    #pragma unroll
    for (int n = 0; n < 4; n++) vmask[n] = (nb + n0 + n < Nn) ? 1.0f : 0.0f;

    // per-row partial sums, reduced across the 16 tx lanes sharing each b
    #pragma unroll
    for (int r = 0; r < 16; r++) {
        float v = ev[r][0] * vmask[0] + ev[r][1] * vmask[1]
                + ev[r][2] * vmask[2] + ev[r][3] * vmask[3];
        v += __shfl_xor_sync(0xFFFFFFFFu, v, 1);
        v += __shfl_xor_sync(0xFFFFFFFFu, v, 2);
        v += __shfl_xor_sync(0xFFFFFFFFu, v, 4);
        v += __shfl_xor_sync(0xFFFFFFFFu, v, 8);
        if (tx == 0) g_Zpart[blockIdx.x * Bq + b0 + r] = v;
    }

    // stores (unnormalized E + mask); vectorized unless tail tile
    const size_t colbase = (size_t)nb + n0;
    if (nb + TILE_N <= Nn) {
        #pragma unroll
        for (int r = 0; r < 16; r++) {
            int gb = b0 + r;
            size_t off = (size_t)gb * Nn + colbase;
            float4 o; o.x = ev[r][0]; o.y = ev[r][1]; o.z = ev[r][2]; o.w = ev[r][3];
            *reinterpret_cast<float4*>(outE + off) = o;
            float bl = blab[gb];
            float4 m;
            m.x = (labf[n0 + 0] == bl) ? 1.0f : 0.0f;
            m.y = (labf[n0 + 1] == bl) ? 1.0f : 0.0f;
            m.z = (labf[n0 + 2] == bl) ? 1.0f : 0.0f;
            m.w = (labf[n0 + 3] == bl) ? 1.0f : 0.0f;
            *reinterpret_cast<float4*>(outM + off) = m;
        }
    } else {
        #pragma unroll
        for (int r = 0; r < 16; r++) {
            int gb = b0 + r;
            float bl = blab[gb];
            #pragma unroll
            for (int n = 0; n < 4; n++) {
                if (colbase + n < (size_t)Nn) {
                    size_t off = (size_t)gb * Nn + colbase + n;
                    outE[off] = ev[r][n];
                    outM[off] = (labf[n0 + n] == bl) ? 1.0f : 0.0f;
                }
            }
        }
    }
}

// ---------------------------------------------------------------------------
// Reduce partials -> invZ[b] = 1 / sum_n exp(.)
// ---------------------------------------------------------------------------
__global__ void nce_reduce()
{
    __shared__ float s[8][Bq];
    int t = threadIdx.x;
    int b = t & 127, c = t >> 7;
    float sum = 0.0f;
    for (int j = c; j < NTILES; j += 8)
        sum += g_Zpart[j * Bq + b];
    s[c][b] = sum;
    __syncthreads();
    if (t < Bq) {
        float z = 0.0f;
        #pragma unroll
        for (int c2 = 0; c2 < 8; c2++) z += s[c2][t];
        g_invZ[t] = 1.0f / z;
    }
}

// ---------------------------------------------------------------------------
// Scale E rows by invZ[b] (pure bandwidth)
// ---------------------------------------------------------------------------
__global__ void nce_scale(float* __restrict__ out)
{
    int b = blockIdx.y;
    float inv = g_invZ[b];
    int i = blockIdx.x * blockDim.x + threadIdx.x;
    if (i < Nn / 4) {
        float4* row = reinterpret_cast<float4*>(out) + (size_t)b * (Nn / 4);
        float4 v = row[i];
        v.x *= inv; v.y *= inv; v.z *= inv; v.w *= inv;
        row[i] = v;
    }
}

// ---------------------------------------------------------------------------
// launch
// inputs: 0=x (128x128 f32), 1=y (unused), 2=labels (128 i32),
//         3=memory_da (100000x129 f32), 4=memory (unused)
// output: concat(out.flatten(), idx_mask.flatten()) as f32
// ---------------------------------------------------------------------------
extern "C" void kernel_launch(void* const* d_in, const int* in_sizes, int n_in,
                              void* d_out, int out_size)
{
    (void)in_sizes; (void)n_in;
    const float* x      = (const float*)d_in[0];
    const int*   labels = (const int*)  d_in[2];
    const float* mda    = (const float*)d_in[3];
    float* out = (float*)d_out;
    size_t half = (size_t)out_size / 2;   // = B*N

    cudaFuncSetAttribute(nce_main, cudaFuncAttributeMaxDynamicSharedMemorySize,
                         SMEM_BYTES);

    nce_main<<<NTILES, 128, SMEM_BYTES>>>(x, labels, mda, out, out + half);
    nce_reduce<<<1, 1024>>>();
    nce_scale<<<dim3((Nn / 4 + 255) / 256, Bq), 256>>>(out);
}

// round 13
// speedup vs baseline: 1.0037x; 1.0037x over previous
#include <cuda_runtime.h>
#include <cstdint>

// Problem constants
#define Bq   128        // batch
#define Nn   100000     // bank size
#define Dd   128        // feature dim
#define ROWS 129        // memory_da row stride (label + 128 feats)
#define TILE_N 64
#define NTILES 1563     // ceil(100000/64)

// exp(dot/T) = 2^(dot * log2(e)/T)
#define KLOG2 20.609929155556620f

// smem layout (floats)
#define XS_OFF   0            // xs: [128 d][132] transposed x  (pad 132)
#define FS_OFF   16896        // fs: [128 d][68]  transposed feats tile (pad 68)
#define LAB_OFF  25600        // [64] tile row labels
#define BLAB_OFF 25664        // [128] batch labels as float
#define SMEM_FLOATS 25792
#define SMEM_BYTES  (SMEM_FLOATS * 4)

// scratch (no allocation allowed -> device globals)
__device__ float g_Zpart[NTILES * Bq];
__device__ float g_invZ[Bq];

// ---------------------------------------------------------------------------
// FFMA-only exp2: 2^t for |t| <= ~40, rel err ~2e-6
// ---------------------------------------------------------------------------
__device__ __forceinline__ float exp2_fast(float t) {
    float r = __fadd_rn(t, 12582912.0f);               // round to int (1.5*2^23)
    float f = __fsub_rn(t, __fsub_rn(r, 12582912.0f)); // f in [-0.5, 0.5]
    int   n = __float_as_int(r) - 0x4B400000;
    float p = 0.00133335581f;
    p = fmaf(p, f, 0.00961812910f);
    p = fmaf(p, f, 0.05550410866f);
    p = fmaf(p, f, 0.24022650696f);
    p = fmaf(p, f, 0.69314718056f);
    p = fmaf(p, f, 1.0f);
    return __int_as_float(__float_as_int(p) + (n << 23));
}

// ---------------------------------------------------------------------------
// Main kernel: 128(b) x 64(n) tile per CTA. 128 threads, thread tile 16b x 4n.
// FFMA2 (fma.rn.f32x2) microkernel, accumulator pairs along b.
//   A loads: 8x ld.shared.b64, only 2 distinct addrs per warp (broadcast).
//   B loads: 1x ld.shared.v4, 16 lanes x 16B contiguous (conflict-free).
// ---------------------------------------------------------------------------
__global__ void __launch_bounds__(128, 2)
nce_main(const float* __restrict__ x,
         const int*   __restrict__ labels,
         const float* __restrict__ mda,
         float* __restrict__ outE,
         float* __restrict__ outM)
{
    extern __shared__ float sm[];
    float* xs   = sm + XS_OFF;    // xs[d*132 + b]
    float* fs   = sm + FS_OFF;    // fs[d*68 + n]
    float* labf = sm + LAB_OFF;
    float* blab = sm + BLAB_OFF;

    const int t  = threadIdx.x;   // 0..127
    const int nb = blockIdx.x * TILE_N;

    // ---- stage x (coalesced LDG across t, d = t) ----
    #pragma unroll 4
    for (int b = 0; b < Bq; b++) {
        xs[t * 132 + b] = x[b * Dd + t];
    }
    // ---- stage feats tile (d = t, one bank row per n) ----
    #pragma unroll 4
    for (int n = 0; n < TILE_N; n++) {
        int gn = nb + n;
        fs[t * 68 + n] = (gn < Nn) ? mda[(size_t)gn * ROWS + 1 + t] : 0.0f;
    }
    if (t < TILE_N) {
        int gn = nb + t;
        labf[t] = (gn < Nn) ? mda[(size_t)gn * ROWS] : -1.0f;
    }
    blab[t] = (float)labels[t];
    __syncthreads();

    const int tx = t & 15, ty = t >> 4;  // tx: n-col group, ty: b-row group
    const int b0 = ty * 16, n0 = tx * 4;

    uint32_t xs_sa = (uint32_t)__cvta_generic_to_shared(xs) + (uint32_t)b0 * 4u;
    uint32_t fs_sa = (uint32_t)__cvta_generic_to_shared(fs) + (uint32_t)n0 * 4u;

    unsigned long long acc[8][4];   // [b-pair 0..7][n 0..3]
    #pragma unroll
    for (int i = 0; i < 8; i++)
        #pragma unroll
        for (int j = 0; j < 4; j++) acc[i][j] = 0ULL;

    #pragma unroll 4
    for (int k = 0; k < 128; k++) {
        unsigned long long a2[8];
        uint32_t aa = xs_sa + (uint32_t)k * 528u;      // 132 floats * 4B
        asm("ld.shared.b64 %0, [%1];"     : "=l"(a2[0]) : "r"(aa));
        asm("ld.shared.b64 %0, [%1+8];"   : "=l"(a2[1]) : "r"(aa));
        asm("ld.shared.b64 %0, [%1+16];"  : "=l"(a2[2]) : "r"(aa));
        asm("ld.shared.b64 %0, [%1+24];"  : "=l"(a2[3]) : "r"(aa));
        asm("ld.shared.b64 %0, [%1+32];"  : "=l"(a2[4]) : "r"(aa));
        asm("ld.shared.b64 %0, [%1+40];"  : "=l"(a2[5]) : "r"(aa));
        asm("ld.shared.b64 %0, [%1+48];"  : "=l"(a2[6]) : "r"(aa));
        asm("ld.shared.b64 %0, [%1+56];"  : "=l"(a2[7]) : "r"(aa));

        float bx, by, bz, bw;
        uint32_t fa = fs_sa + (uint32_t)k * 272u;      // 68 floats * 4B
        asm("ld.shared.v4.f32 {%0,%1,%2,%3}, [%4];"
            : "=f"(bx), "=f"(by), "=f"(bz), "=f"(bw) : "r"(fa));

        unsigned long long b2[4];
        asm("mov.b64 %0, {%1,%2};" : "=l"(b2[0]) : "f"(bx), "f"(bx));
        asm("mov.b64 %0, {%1,%2};" : "=l"(b2[1]) : "f"(by), "f"(by));
        asm("mov.b64 %0, {%1,%2};" : "=l"(b2[2]) : "f"(bz), "f"(bz));
        asm("mov.b64 %0, {%1,%2};" : "=l"(b2[3]) : "f"(bw), "f"(bw));

        #pragma unroll
        for (int bp = 0; bp < 8; bp++)
            #pragma unroll
            for (int n = 0; n < 4; n++)
                asm("fma.rn.f32x2 %0, %1, %2, %0;"
                    : "+l"(acc[bp][n]) : "l"(a2[bp]), "l"(b2[n]));
    }

    // ---- epilogue: exp, partial sums, stores ----
    float ev[16][4];
    #pragma unroll
    for (int bp = 0; bp < 8; bp++) {
        #pragma unroll
        for (int n = 0; n < 4; n++) {
            float lo, hi;
            asm("mov.b64 {%0,%1}, %2;" : "=f"(lo), "=f"(hi) : "l"(acc[bp][n]));
            ev[2 * bp + 0][n] = exp2_fast(lo * KLOG2);
            ev[2 * bp + 1][n] = exp2_fast(hi * KLOG2);
        }
    }

    float vmask[4];
    #pragma unroll
    for (int n = 0; n < 4; n++) vmask[n] = (nb + n0 + n < Nn) ? 1.0f : 0.0f;

    // per-row partial sums, reduced across the 16 tx lanes sharing each b
    #pragma unroll
    for (int r = 0; r < 16; r++) {
        float v = ev[r][0] * vmask[0] + ev[r][1] * vmask[1]
                + ev[r][2] * vmask[2] + ev[r][3] * vmask[3];
        v += __shfl_xor_sync(0xFFFFFFFFu, v, 1);
        v += __shfl_xor_sync(0xFFFFFFFFu, v, 2);
        v += __shfl_xor_sync(0xFFFFFFFFu, v, 4);
        v += __shfl_xor_sync(0xFFFFFFFFu, v, 8);
        if (tx == 0) g_Zpart[blockIdx.x * Bq + b0 + r] = v;
    }

    // stores (unnormalized E + mask); vectorized unless tail tile
    const size_t colbase = (size_t)nb + n0;
    if (nb + TILE_N <= Nn) {
        #pragma unroll
        for (int r = 0; r < 16; r++) {
            int gb = b0 + r;
            size_t off = (size_t)gb * Nn + colbase;
            float4 o; o.x = ev[r][0]; o.y = ev[r][1]; o.z = ev[r][2]; o.w = ev[r][3];
            *reinterpret_cast<float4*>(outE + off) = o;
            float bl = blab[gb];
            float4 m;
            m.x = (labf[n0 + 0] == bl) ? 1.0f : 0.0f;
            m.y = (labf[n0 + 1] == bl) ? 1.0f : 0.0f;
            m.z = (labf[n0 + 2] == bl) ? 1.0f : 0.0f;
            m.w = (labf[n0 + 3] == bl) ? 1.0f : 0.0f;
            *reinterpret_cast<float4*>(outM + off) = m;
        }
    } else {
        #pragma unroll
        for (int r = 0; r < 16; r++) {
            int gb = b0 + r;
            float bl = blab[gb];
            #pragma unroll
            for (int n = 0; n < 4; n++) {
                if (colbase + n < (size_t)Nn) {
                    size_t off = (size_t)gb * Nn + colbase + n;
                    outE[off] = ev[r][n];
                    outM[off] = (labf[n0 + n] == bl) ? 1.0f : 0.0f;
                }
            }
        }
    }
}

// ---------------------------------------------------------------------------
// Reduce partials -> invZ[b] = 1 / sum_n exp(.)
// ---------------------------------------------------------------------------
__global__ void nce_reduce()
{
    __shared__ float s[8][Bq];
    int t = threadIdx.x;
    int b = t & 127, c = t >> 7;
    float sum = 0.0f;
    for (int j = c; j < NTILES; j += 8)
        sum += g_Zpart[j * Bq + b];
    s[c][b] = sum;
    __syncthreads();
    if (t < Bq) {
        float z = 0.0f;
        #pragma unroll
        for (int c2 = 0; c2 < 8; c2++) z += s[c2][t];
        g_invZ[t] = 1.0f / z;
    }
}

// ---------------------------------------------------------------------------
// Scale E rows by invZ[b] (pure bandwidth)
// ---------------------------------------------------------------------------
__global__ void nce_scale(float* __restrict__ out)
{
    int b = blockIdx.y;
    float inv = g_invZ[b];
    int i = blockIdx.x * blockDim.x + threadIdx.x;
    if (i < Nn / 4) {
        float4* row = reinterpret_cast<float4*>(out) + (size_t)b * (Nn / 4);
        float4 v = row[i];
        v.x *= inv; v.y *= inv; v.z *= inv; v.w *= inv;
        row[i] = v;
    }
}

// ---------------------------------------------------------------------------
// launch
// inputs: 0=x (128x128 f32), 1=y (unused), 2=labels (128 i32),
//         3=memory_da (100000x129 f32), 4=memory (unused)
// output: concat(out.flatten(), idx_mask.flatten()) as f32
// ---------------------------------------------------------------------------
extern "C" void kernel_launch(void* const* d_in, const int* in_sizes, int n_in,
                              void* d_out, int out_size)
{
    (void)in_sizes; (void)n_in;
    const float* x      = (const float*)d_in[0];
    const int*   labels = (const int*)  d_in[2];
    const float* mda    = (const float*)d_in[3];
    float* out = (float*)d_out;
    size_t half = (size_t)out_size / 2;   // = B*N

    cudaFuncSetAttribute(nce_main, cudaFuncAttributeMaxDynamicSharedMemorySize,
                         SMEM_BYTES);

    nce_main<<<NTILES, 128, SMEM_BYTES>>>(x, labels, mda, out, out + half);
    nce_reduce<<<1, 1024>>>();
    nce_scale<<<dim3((Nn / 4 + 255) / 256, Bq), 256>>>(out);
}